// round 1
// baseline (speedup 1.0000x reference)
#include <cuda_runtime.h>
#include <math.h>

#define S_LEN 4096
#define D_MODEL 1024
#define NH 16
#define HD 64

// Scratch (allocation-free requirement -> __device__ globals)
__device__ float g_qkv[(size_t)S_LEN * 3 * D_MODEL];  // [S, 3D]
__device__ float g_ctx[(size_t)S_LEN * D_MODEL];      // [S, D]

// ---------------------------------------------------------------------------
// GEMM: C[M,N] = A[M,K] @ B[K,N] + bias[N]   (all row-major fp32)
// 128x128 block tile, BK=16, 256 threads, 8x8 per-thread micro-tile.
// ---------------------------------------------------------------------------
#define BM 128
#define BN 128
#define BK 16

__global__ __launch_bounds__(256) void gemm_bias_kernel(
    const float* __restrict__ A, const float* __restrict__ B,
    const float* __restrict__ bias, float* __restrict__ C,
    int M, int N, int K)
{
    __shared__ float AsT[BK][132];   // A tile transposed, padded stride
    __shared__ float Bs[BK][BN];

    const int tid  = threadIdx.x;
    const int cRow = tid >> 4;       // 0..15
    const int cCol = tid & 15;       // 0..15
    const int m0 = blockIdx.y * BM;
    const int n0 = blockIdx.x * BN;

    float acc[8][8];
    #pragma unroll
    for (int i = 0; i < 8; ++i)
        #pragma unroll
        for (int j = 0; j < 8; ++j) acc[i][j] = 0.f;

    const float* Ab = A + (size_t)m0 * K;
    const float* Bb = B + n0;

    for (int k0 = 0; k0 < K; k0 += BK) {
        // Load A tile (128 x 16) -> AsT[k][m]
        #pragma unroll
        for (int t = 0; t < 2; ++t) {
            int idx = tid + t * 256;       // 0..511 float4s
            int row = idx >> 2;            // 0..127
            int kq  = (idx & 3) << 2;      // 0,4,8,12
            float4 v = *(const float4*)(Ab + (size_t)row * K + k0 + kq);
            AsT[kq + 0][row] = v.x;
            AsT[kq + 1][row] = v.y;
            AsT[kq + 2][row] = v.z;
            AsT[kq + 3][row] = v.w;
        }
        // Load B tile (16 x 128) -> Bs[k][n]
        #pragma unroll
        for (int t = 0; t < 2; ++t) {
            int idx = tid + t * 256;
            int row = idx >> 5;            // 0..15
            int nq  = (idx & 31) << 2;     // 0..124
            *(float4*)&Bs[row][nq] = *(const float4*)(Bb + (size_t)(k0 + row) * N + nq);
        }
        __syncthreads();

        #pragma unroll
        for (int k = 0; k < BK; ++k) {
            float a[8], b[8];
            *(float4*)(a)     = *(const float4*)&AsT[k][cRow * 8];
            *(float4*)(a + 4) = *(const float4*)&AsT[k][cRow * 8 + 4];
            *(float4*)(b)     = *(const float4*)&Bs[k][cCol * 8];
            *(float4*)(b + 4) = *(const float4*)&Bs[k][cCol * 8 + 4];
            #pragma unroll
            for (int i = 0; i < 8; ++i)
                #pragma unroll
                for (int j = 0; j < 8; ++j)
                    acc[i][j] = fmaf(a[i], b[j], acc[i][j]);
        }
        __syncthreads();
    }

    float bj[8];
    #pragma unroll
    for (int j = 0; j < 8; ++j) bj[j] = bias[n0 + cCol * 8 + j];
    #pragma unroll
    for (int i = 0; i < 8; ++i) {
        float* Crow = C + (size_t)(m0 + cRow * 8 + i) * N + n0 + cCol * 8;
        float4 v0 = make_float4(acc[i][0] + bj[0], acc[i][1] + bj[1],
                                acc[i][2] + bj[2], acc[i][3] + bj[3]);
        float4 v1 = make_float4(acc[i][4] + bj[4], acc[i][5] + bj[5],
                                acc[i][6] + bj[6], acc[i][7] + bj[7]);
        *(float4*)(Crow)     = v0;
        *(float4*)(Crow + 4) = v1;
    }
}

// ---------------------------------------------------------------------------
// Flash attention (fp32, causal). One block per (head, 64-query tile).
// 256 threads as 16x16, 4x4 micro-tiles for both S=QK^T and O=PV.
// K tile stored transposed (stride 66); P reuses the K buffer.
// ---------------------------------------------------------------------------
#define KP_STRIDE 66

__global__ __launch_bounds__(256) void attn_kernel(
    const float* __restrict__ qkv, float* __restrict__ ctx)
{
    extern __shared__ float sm[];
    float* Qs = sm;                        // [64][64]
    float* KP = sm + 64 * 64;              // [64][KP_STRIDE]  K^T, then P
    float* Vs = KP + 64 * KP_STRIDE;       // [64][64]

    const int h   = blockIdx.y;
    const int qt  = 63 - blockIdx.x;       // heavy (long) tiles first
    const int q0  = qt * 64;
    const int tid = threadIdx.x;
    const int r   = tid >> 4;              // 0..15 -> query group
    const int c   = tid & 15;              // 0..15 -> key/dim group

    // Load Q tile, pre-scaled by 1/sqrt(HD)
    const float* qb = qkv + (size_t)q0 * (3 * D_MODEL) + h * HD;
    for (int idx = tid; idx < 4096; idx += 256) {
        int q = idx >> 6, d = idx & 63;
        Qs[q * 64 + d] = qb[(size_t)q * (3 * D_MODEL) + d] * 0.125f;
    }

    float m[4], l[4], o[4][4];
    #pragma unroll
    for (int i = 0; i < 4; ++i) {
        m[i] = -1e30f; l[i] = 0.f;
        #pragma unroll
        for (int j = 0; j < 4; ++j) o[i][j] = 0.f;
    }

    const float* kb = qkv + D_MODEL + h * HD;
    const float* vb = qkv + 2 * D_MODEL + h * HD;

    for (int kt = 0; kt <= qt; ++kt) {
        __syncthreads();   // previous iteration done with KP/Vs
        for (int idx = tid; idx < 4096; idx += 256) {
            int k = idx >> 6, d = idx & 63;
            size_t g = (size_t)(kt * 64 + k) * (3 * D_MODEL) + d;
            KP[d * KP_STRIDE + k] = kb[g];   // transposed
            Vs[k * 64 + d]        = vb[g];
        }
        __syncthreads();

        // S = Q K^T (4x4 per thread)
        float s[4][4];
        #pragma unroll
        for (int i = 0; i < 4; ++i)
            #pragma unroll
            for (int j = 0; j < 4; ++j) s[i][j] = 0.f;

        for (int kk = 0; kk < 64; ++kk) {
            float qv[4];
            #pragma unroll
            for (int i = 0; i < 4; ++i) qv[i] = Qs[(r * 4 + i) * 64 + kk];
            float2 k01 = *(const float2*)&KP[kk * KP_STRIDE + c * 4];
            float2 k23 = *(const float2*)&KP[kk * KP_STRIDE + c * 4 + 2];
            float kv[4] = {k01.x, k01.y, k23.x, k23.y};
            #pragma unroll
            for (int i = 0; i < 4; ++i)
                #pragma unroll
                for (int j = 0; j < 4; ++j)
                    s[i][j] = fmaf(qv[i], kv[j], s[i][j]);
        }

        // Causal mask on diagonal tile
        if (kt == qt) {
            #pragma unroll
            for (int i = 0; i < 4; ++i)
                #pragma unroll
                for (int j = 0; j < 4; ++j)
                    if (c * 4 + j > r * 4 + i) s[i][j] = -1e30f;
        }

        // Online softmax (row stats shared by the 16 lanes of a row group)
        #pragma unroll
        for (int i = 0; i < 4; ++i) {
            float tm = fmaxf(fmaxf(s[i][0], s[i][1]), fmaxf(s[i][2], s[i][3]));
            #pragma unroll
            for (int off = 1; off < 16; off <<= 1)
                tm = fmaxf(tm, __shfl_xor_sync(0xffffffffu, tm, off));
            float mn = fmaxf(m[i], tm);
            float rs = 0.f;
            #pragma unroll
            for (int j = 0; j < 4; ++j) {
                float p = __expf(s[i][j] - mn);
                s[i][j] = p;
                rs += p;
            }
            #pragma unroll
            for (int off = 1; off < 16; off <<= 1)
                rs += __shfl_xor_sync(0xffffffffu, rs, off);
            float alpha = __expf(m[i] - mn);
            l[i] = l[i] * alpha + rs;
            #pragma unroll
            for (int j = 0; j < 4; ++j) o[i][j] *= alpha;
            m[i] = mn;
        }

        // P -> smem (reuse K buffer), then O += P V
        __syncthreads();
        #pragma unroll
        for (int i = 0; i < 4; ++i) {
            float* prow = &KP[(r * 4 + i) * KP_STRIDE + c * 4];
            *(float2*)(prow)     = make_float2(s[i][0], s[i][1]);
            *(float2*)(prow + 2) = make_float2(s[i][2], s[i][3]);
        }
        __syncthreads();

        for (int k = 0; k < 64; ++k) {
            float pv[4];
            #pragma unroll
            for (int i = 0; i < 4; ++i) pv[i] = KP[(r * 4 + i) * KP_STRIDE + k];
            float4 vv = *(const float4*)&Vs[k * 64 + c * 4];
            #pragma unroll
            for (int i = 0; i < 4; ++i) {
                o[i][0] = fmaf(pv[i], vv.x, o[i][0]);
                o[i][1] = fmaf(pv[i], vv.y, o[i][1]);
                o[i][2] = fmaf(pv[i], vv.z, o[i][2]);
                o[i][3] = fmaf(pv[i], vv.w, o[i][3]);
            }
        }
    }

    // Write ctx[q, h*64 + d] (layout [S, D] ready for the proj GEMM)
    float* ob = ctx + (size_t)q0 * D_MODEL + h * HD;
    #pragma unroll
    for (int i = 0; i < 4; ++i) {
        int q = r * 4 + i;
        float inv = 1.f / l[i];
        float4 v = make_float4(o[i][0] * inv, o[i][1] * inv,
                               o[i][2] * inv, o[i][3] * inv);
        *(float4*)(ob + (size_t)q * D_MODEL + c * 4) = v;
    }
}

// ---------------------------------------------------------------------------
// Launch
// ---------------------------------------------------------------------------
extern "C" void kernel_launch(void* const* d_in, const int* in_sizes, int n_in,
                              void* d_out, int out_size)
{
    const float* x      = (const float*)d_in[0];
    const float* w_qkv  = (const float*)d_in[1];
    const float* b_qkv  = (const float*)d_in[2];
    const float* w_proj = (const float*)d_in[3];
    const float* b_proj = (const float*)d_in[4];
    float* out = (float*)d_out;

    float *qkv_ptr, *ctx_ptr;
    cudaGetSymbolAddress((void**)&qkv_ptr, g_qkv);
    cudaGetSymbolAddress((void**)&ctx_ptr, g_ctx);

    const int attn_smem = (64 * 64 + 64 * KP_STRIDE + 64 * 64) * (int)sizeof(float);
    cudaFuncSetAttribute(attn_kernel, cudaFuncAttributeMaxDynamicSharedMemorySize, attn_smem);

    // 1) qkv = x @ w_qkv + b_qkv            [4096, 3072]
    gemm_bias_kernel<<<dim3(3 * D_MODEL / BN, S_LEN / BM), 256>>>(
        x, w_qkv, b_qkv, qkv_ptr, S_LEN, 3 * D_MODEL, D_MODEL);

    // 2) causal flash attention -> ctx      [4096, 1024]
    attn_kernel<<<dim3(64, NH), 256, attn_smem>>>(qkv_ptr, ctx_ptr);

    // 3) out = ctx @ w_proj + b_proj        [4096, 1024]
    gemm_bias_kernel<<<dim3(D_MODEL / BN, S_LEN / BM), 256>>>(
        ctx_ptr, w_proj, b_proj, out, S_LEN, D_MODEL, D_MODEL);
}

// round 2
// speedup vs baseline: 2.4242x; 2.4242x over previous
#include <cuda_runtime.h>
#include <math.h>

#define S_LEN 4096
#define D_MODEL 1024
#define NH 16
#define HD 64

// Scratch (allocation-free requirement -> __device__ globals)
__device__ float g_qkv[(size_t)S_LEN * 3 * D_MODEL];  // [S, 3D]
__device__ float g_ctx[(size_t)S_LEN * D_MODEL];      // [S, D]

// ---------------------------------------------------------------------------
// tf32 helpers
// ---------------------------------------------------------------------------
__device__ __forceinline__ unsigned f2tf(float f) {
    unsigned u;
    asm("cvt.rna.tf32.f32 %0, %1;" : "=r"(u) : "f"(f));
    return u;
}

__device__ __forceinline__ void mma8(float* d, const unsigned* a, const unsigned* b) {
    asm volatile("mma.sync.aligned.m16n8k8.row.col.f32.tf32.tf32.f32 "
        "{%0,%1,%2,%3}, {%4,%5,%6,%7}, {%8,%9}, {%0,%1,%2,%3};"
        : "+f"(d[0]), "+f"(d[1]), "+f"(d[2]), "+f"(d[3])
        : "r"(a[0]), "r"(a[1]), "r"(a[2]), "r"(a[3]), "r"(b[0]), "r"(b[1]));
}

// ---------------------------------------------------------------------------
// GEMM: C[M,N] = A[M,K] @ B[K,N] + bias  (fp32 in/out, tf32 tensor-core mma)
// 128x128 block, BK=16, 256 threads (8 warps, 4x2), warp tile 32x64.
// ---------------------------------------------------------------------------
#define BM 128
#define BN 128
#define BK 16
#define ASTR 20    // 20 mod 32: banks 20g+t conflict-free for g0..7,t0..3
#define BSTR 136   // 136 mod 32 = 8: banks 8t+g conflict-free

__global__ __launch_bounds__(256) void gemm_tf32_kernel(
    const float* __restrict__ A, const float* __restrict__ B,
    const float* __restrict__ bias, float* __restrict__ C,
    int M, int N, int K)
{
    __shared__ unsigned As[BM][ASTR];
    __shared__ unsigned Bs[BK][BSTR];

    const int tid  = threadIdx.x;
    const int warp = tid >> 5, lane = tid & 31;
    const int g = lane >> 2, t = lane & 3;
    const int wm = (warp & 3) * 32;
    const int wn = (warp >> 2) * 64;
    const int m0 = blockIdx.y * BM, n0 = blockIdx.x * BN;

    float acc[2][8][4];
    #pragma unroll
    for (int mt = 0; mt < 2; ++mt)
        #pragma unroll
        for (int nt = 0; nt < 8; ++nt)
            #pragma unroll
            for (int i = 0; i < 4; ++i) acc[mt][nt][i] = 0.f;

    for (int k0 = 0; k0 < K; k0 += BK) {
        // A tile 128x16 -> As (tf32)
        #pragma unroll
        for (int tt = 0; tt < 2; ++tt) {
            int idx = tid + tt * 256;          // 0..511
            int row = idx >> 2, kq = (idx & 3) << 2;
            float4 v = *(const float4*)(A + (size_t)(m0 + row) * K + k0 + kq);
            unsigned* d = &As[row][kq];
            d[0] = f2tf(v.x); d[1] = f2tf(v.y); d[2] = f2tf(v.z); d[3] = f2tf(v.w);
        }
        // B tile 16x128 -> Bs (tf32)
        #pragma unroll
        for (int tt = 0; tt < 2; ++tt) {
            int idx = tid + tt * 256;
            int row = idx >> 5, nq = (idx & 31) << 2;
            float4 v = *(const float4*)(B + (size_t)(k0 + row) * N + n0 + nq);
            unsigned* d = &Bs[row][nq];
            d[0] = f2tf(v.x); d[1] = f2tf(v.y); d[2] = f2tf(v.z); d[3] = f2tf(v.w);
        }
        __syncthreads();

        #pragma unroll
        for (int ks = 0; ks < 2; ++ks) {
            unsigned a[2][4], b[8][2];
            #pragma unroll
            for (int mt = 0; mt < 2; ++mt) {
                int r = wm + mt * 16;
                a[mt][0] = As[r + g][ks * 8 + t];
                a[mt][1] = As[r + g + 8][ks * 8 + t];
                a[mt][2] = As[r + g][ks * 8 + t + 4];
                a[mt][3] = As[r + g + 8][ks * 8 + t + 4];
            }
            #pragma unroll
            for (int nt = 0; nt < 8; ++nt) {
                b[nt][0] = Bs[ks * 8 + t][wn + nt * 8 + g];
                b[nt][1] = Bs[ks * 8 + t + 4][wn + nt * 8 + g];
            }
            #pragma unroll
            for (int mt = 0; mt < 2; ++mt)
                #pragma unroll
                for (int nt = 0; nt < 8; ++nt)
                    mma8(acc[mt][nt], a[mt], b[nt]);
        }
        __syncthreads();
    }

    #pragma unroll
    for (int mt = 0; mt < 2; ++mt) {
        int row = m0 + wm + mt * 16 + g;
        #pragma unroll
        for (int nt = 0; nt < 8; ++nt) {
            int col = n0 + wn + nt * 8 + 2 * t;
            float b0 = bias[col], b1 = bias[col + 1];
            *(float2*)(C + (size_t)row * N + col) =
                make_float2(acc[mt][nt][0] + b0, acc[mt][nt][1] + b1);
            *(float2*)(C + (size_t)(row + 8) * N + col) =
                make_float2(acc[mt][nt][2] + b0, acc[mt][nt][3] + b1);
        }
    }
}

// ---------------------------------------------------------------------------
// Flash attention, tf32 tensor cores. Block = (head, 128-query tile).
// 8 warps; each warp owns 16 query rows x all 64 keys of the K-tile.
// ---------------------------------------------------------------------------
#define BQ 128
#define BKV 64
#define QSTR 68   // 68 mod 32 = 4: banks 4g+t conflict-free (row-indexed by g)
#define KSTR 68
#define VSTR 72   // 72 mod 32 = 8: banks 8t+g conflict-free (row-indexed by t)
#define PSTR 68

__global__ __launch_bounds__(256) void attn_tf32_kernel(
    const float* __restrict__ qkv, float* __restrict__ ctx)
{
    extern __shared__ unsigned smem[];
    unsigned* Qs = smem;                  // [128][QSTR]
    unsigned* Ks = Qs + BQ * QSTR;        // [64][KSTR]
    unsigned* Vs = Ks + BKV * KSTR;       // [64][VSTR]
    unsigned* Ps = Vs + BKV * VSTR;       // [8 warps][16][PSTR]

    const int h  = blockIdx.y;
    const int qt = (int)gridDim.x - 1 - (int)blockIdx.x;   // heavy tiles first
    const int q0 = qt * BQ;
    const int tid = threadIdx.x;
    const int warp = tid >> 5, lane = tid & 31;
    const int g = lane >> 2, t = lane & 3;
    const int wm = warp * 16;
    unsigned* Pw = Ps + warp * 16 * PSTR;

    // Load Q tile (pre-scaled by 1/sqrt(HD) = 0.125), tf32
    const float* qb = qkv + (size_t)q0 * (3 * D_MODEL) + h * HD;
    for (int idx = tid; idx < BQ * 16; idx += 256) {
        int row = idx >> 4, dq = (idx & 15) << 2;
        float4 v = *(const float4*)(qb + (size_t)row * (3 * D_MODEL) + dq);
        unsigned* d = &Qs[row * QSTR + dq];
        d[0] = f2tf(v.x * 0.125f); d[1] = f2tf(v.y * 0.125f);
        d[2] = f2tf(v.z * 0.125f); d[3] = f2tf(v.w * 0.125f);
    }

    float m_[2] = {-1e30f, -1e30f};
    float l_[2] = {0.f, 0.f};
    float o[8][4];
    #pragma unroll
    for (int nt = 0; nt < 8; ++nt)
        #pragma unroll
        for (int i = 0; i < 4; ++i) o[nt][i] = 0.f;

    const float* kb = qkv + D_MODEL + h * HD;
    const float* vb = qkv + 2 * D_MODEL + h * HD;
    const int nkt = 2 * qt + 2;

    for (int kt = 0; kt < nkt; ++kt) {
        __syncthreads();
        // Load K,V tiles (64x64 each), tf32
        for (int idx = tid; idx < BKV * 16; idx += 256) {
            int row = idx >> 4, dq = (idx & 15) << 2;
            size_t go = (size_t)(kt * BKV + row) * (3 * D_MODEL) + dq;
            float4 kv = *(const float4*)(kb + go);
            unsigned* kd = &Ks[row * KSTR + dq];
            kd[0] = f2tf(kv.x); kd[1] = f2tf(kv.y); kd[2] = f2tf(kv.z); kd[3] = f2tf(kv.w);
            float4 vv = *(const float4*)(vb + go);
            unsigned* vd = &Vs[row * VSTR + dq];
            vd[0] = f2tf(vv.x); vd[1] = f2tf(vv.y); vd[2] = f2tf(vv.z); vd[3] = f2tf(vv.w);
        }
        __syncthreads();

        // Skip fully-masked warps (rows wm..wm+15 all < kt*64)
        if (kt * BKV > q0 + wm + 15) continue;

        // S = Q K^T   (16 x 64 per warp)
        float s[8][4];
        #pragma unroll
        for (int nt = 0; nt < 8; ++nt)
            #pragma unroll
            for (int i = 0; i < 4; ++i) s[nt][i] = 0.f;

        #pragma unroll
        for (int ks = 0; ks < 8; ++ks) {
            unsigned a[4];
            a[0] = Qs[(wm + g) * QSTR + ks * 8 + t];
            a[1] = Qs[(wm + g + 8) * QSTR + ks * 8 + t];
            a[2] = Qs[(wm + g) * QSTR + ks * 8 + t + 4];
            a[3] = Qs[(wm + g + 8) * QSTR + ks * 8 + t + 4];
            #pragma unroll
            for (int nt = 0; nt < 8; ++nt) {
                unsigned b[2];
                b[0] = Ks[(nt * 8 + g) * KSTR + ks * 8 + t];
                b[1] = Ks[(nt * 8 + g) * KSTR + ks * 8 + t + 4];
                mma8(s[nt], a, b);
            }
        }

        // Causal mask (only the two diagonal k-tiles can mask anything)
        if (kt >= 2 * qt) {
            int r0 = q0 + wm + g;
            #pragma unroll
            for (int nt = 0; nt < 8; ++nt) {
                int col = kt * BKV + nt * 8 + 2 * t;
                if (col     > r0)     s[nt][0] = -1e30f;
                if (col + 1 > r0)     s[nt][1] = -1e30f;
                if (col     > r0 + 8) s[nt][2] = -1e30f;
                if (col + 1 > r0 + 8) s[nt][3] = -1e30f;
            }
        }

        // Online softmax (rows g and g+8; stats over 4 lanes of the quad)
        #pragma unroll
        for (int r = 0; r < 2; ++r) {
            float tm = -1e30f;
            #pragma unroll
            for (int nt = 0; nt < 8; ++nt)
                tm = fmaxf(tm, fmaxf(s[nt][2 * r], s[nt][2 * r + 1]));
            tm = fmaxf(tm, __shfl_xor_sync(0xffffffffu, tm, 1));
            tm = fmaxf(tm, __shfl_xor_sync(0xffffffffu, tm, 2));
            float mn = fmaxf(m_[r], tm);
            float rs = 0.f;
            #pragma unroll
            for (int nt = 0; nt < 8; ++nt) {
                float p0 = __expf(s[nt][2 * r] - mn);
                float p1 = __expf(s[nt][2 * r + 1] - mn);
                s[nt][2 * r] = p0; s[nt][2 * r + 1] = p1;
                rs += p0 + p1;
            }
            rs += __shfl_xor_sync(0xffffffffu, rs, 1);
            rs += __shfl_xor_sync(0xffffffffu, rs, 2);
            float alpha = __expf(m_[r] - mn);
            l_[r] = l_[r] * alpha + rs;
            #pragma unroll
            for (int nt = 0; nt < 8; ++nt) {
                o[nt][2 * r] *= alpha; o[nt][2 * r + 1] *= alpha;
            }
            m_[r] = mn;
        }

        // P -> warp-private smem (tf32), then O += P V
        __syncwarp();
        #pragma unroll
        for (int nt = 0; nt < 8; ++nt) {
            unsigned* p0 = &Pw[g * PSTR + nt * 8 + 2 * t];
            p0[0] = f2tf(s[nt][0]); p0[1] = f2tf(s[nt][1]);
            unsigned* p1 = &Pw[(g + 8) * PSTR + nt * 8 + 2 * t];
            p1[0] = f2tf(s[nt][2]); p1[1] = f2tf(s[nt][3]);
        }
        __syncwarp();

        #pragma unroll
        for (int ks = 0; ks < 8; ++ks) {
            unsigned a[4];
            a[0] = Pw[g * PSTR + ks * 8 + t];
            a[1] = Pw[(g + 8) * PSTR + ks * 8 + t];
            a[2] = Pw[g * PSTR + ks * 8 + t + 4];
            a[3] = Pw[(g + 8) * PSTR + ks * 8 + t + 4];
            #pragma unroll
            for (int nt = 0; nt < 8; ++nt) {
                unsigned b[2];
                b[0] = Vs[(ks * 8 + t) * VSTR + nt * 8 + g];
                b[1] = Vs[(ks * 8 + t + 4) * VSTR + nt * 8 + g];
                mma8(o[nt], a, b);
            }
        }
    }

    // Epilogue: normalize and write ctx[q, h*64+d]
    float inv0 = 1.f / l_[0], inv1 = 1.f / l_[1];
    float* ob = ctx + (size_t)(q0 + wm) * D_MODEL + h * HD;
    #pragma unroll
    for (int nt = 0; nt < 8; ++nt) {
        int col = nt * 8 + 2 * t;
        *(float2*)(ob + (size_t)g * D_MODEL + col) =
            make_float2(o[nt][0] * inv0, o[nt][1] * inv0);
        *(float2*)(ob + (size_t)(g + 8) * D_MODEL + col) =
            make_float2(o[nt][2] * inv1, o[nt][3] * inv1);
    }
}

// ---------------------------------------------------------------------------
// Launch
// ---------------------------------------------------------------------------
extern "C" void kernel_launch(void* const* d_in, const int* in_sizes, int n_in,
                              void* d_out, int out_size)
{
    const float* x      = (const float*)d_in[0];
    const float* w_qkv  = (const float*)d_in[1];
    const float* b_qkv  = (const float*)d_in[2];
    const float* w_proj = (const float*)d_in[3];
    const float* b_proj = (const float*)d_in[4];
    float* out = (float*)d_out;

    float *qkv_ptr, *ctx_ptr;
    cudaGetSymbolAddress((void**)&qkv_ptr, g_qkv);
    cudaGetSymbolAddress((void**)&ctx_ptr, g_ctx);

    const int attn_smem =
        (BQ * QSTR + BKV * KSTR + BKV * VSTR + 8 * 16 * PSTR) * (int)sizeof(unsigned);
    cudaFuncSetAttribute(attn_tf32_kernel,
                         cudaFuncAttributeMaxDynamicSharedMemorySize, attn_smem);

    // 1) qkv = x @ w_qkv + b_qkv            [4096, 3072]
    gemm_tf32_kernel<<<dim3(3 * D_MODEL / BN, S_LEN / BM), 256>>>(
        x, w_qkv, b_qkv, qkv_ptr, S_LEN, 3 * D_MODEL, D_MODEL);

    // 2) causal flash attention -> ctx      [4096, 1024]
    attn_tf32_kernel<<<dim3(S_LEN / BQ, NH), 256, attn_smem>>>(qkv_ptr, ctx_ptr);

    // 3) out = ctx @ w_proj + b_proj        [4096, 1024]
    gemm_tf32_kernel<<<dim3(D_MODEL / BN, S_LEN / BM), 256>>>(
        ctx_ptr, w_proj, b_proj, out, S_LEN, D_MODEL, D_MODEL);
}

// round 4
// speedup vs baseline: 2.8622x; 1.1806x over previous
#include <cuda_runtime.h>
#include <math.h>

#define S_LEN 4096
#define D_MODEL 1024
#define NH 16
#define HD 64

// Scratch (allocation-free requirement -> __device__ globals)
__device__ float g_qkv[(size_t)S_LEN * 3 * D_MODEL];  // [S, 3D]
__device__ float g_ctx[(size_t)S_LEN * D_MODEL];      // [S, D]

// ---------------------------------------------------------------------------
// tf32 helpers
// ---------------------------------------------------------------------------
__device__ __forceinline__ unsigned f2tf(float f) {
    unsigned u;
    asm("cvt.rna.tf32.f32 %0, %1;" : "=r"(u) : "f"(f));
    return u;
}

__device__ __forceinline__ void mma8(float* d, const unsigned* a, const unsigned* b) {
    asm volatile("mma.sync.aligned.m16n8k8.row.col.f32.tf32.tf32.f32 "
        "{%0,%1,%2,%3}, {%4,%5,%6,%7}, {%8,%9}, {%0,%1,%2,%3};"
        : "+f"(d[0]), "+f"(d[1]), "+f"(d[2]), "+f"(d[3])
        : "r"(a[0]), "r"(a[1]), "r"(a[2]), "r"(a[3]), "r"(b[0]), "r"(b[1]));
}

// ---------------------------------------------------------------------------
// GEMM: C[M,N] = A[M,K] @ B[K,N] + bias  (fp32 in/out, tf32 mma)
// 128x128 block, BK=16, 256 threads (8 warps, 4x2), warp tile 32x64.
// Double-buffered smem + register prefetch: 1 syncthreads per BK-iter.
// ---------------------------------------------------------------------------
#define BM 128
#define BN 128
#define BK 16
#define ASTR 20    // 20 mod 32 = 20: banks (20g+t)%32 == (4g+t+16g)%32 conflict-free
#define BSTR 136   // 136 mod 32 = 8: banks 8t+g conflict-free

__global__ __launch_bounds__(256, 2) void gemm_tf32_kernel(
    const float* __restrict__ A, const float* __restrict__ B,
    const float* __restrict__ bias, float* __restrict__ C,
    int M, int N, int K)
{
    __shared__ unsigned As[2][BM][ASTR];
    __shared__ unsigned Bs[2][BK][BSTR];

    const int tid  = threadIdx.x;
    const int warp = tid >> 5, lane = tid & 31;
    const int g = lane >> 2, t = lane & 3;
    const int wm = (warp & 3) * 32;
    const int wn = (warp >> 2) * 64;
    const int m0 = blockIdx.y * BM, n0 = blockIdx.x * BN;

    // Per-thread load slots (2 float4s of A, 2 of B)
    const int arow0 = tid >> 2, akq = (tid & 3) << 2;   // rows 0..63
    const int arow1 = arow0 + 64;                       // rows 64..127
    const int brow0 = tid >> 5, bnq = (tid & 31) << 2;  // rows 0..7
    const int brow1 = brow0 + 8;                        // rows 8..15

    float acc[2][8][4];
    #pragma unroll
    for (int mt = 0; mt < 2; ++mt)
        #pragma unroll
        for (int nt = 0; nt < 8; ++nt)
            #pragma unroll
            for (int i = 0; i < 4; ++i) acc[mt][nt][i] = 0.f;

    float4 ra0, ra1, rb0, rb1;

    // prologue: tile 0 -> buf 0
    ra0 = *(const float4*)(A + (size_t)(m0 + arow0) * K + akq);
    ra1 = *(const float4*)(A + (size_t)(m0 + arow1) * K + akq);
    rb0 = *(const float4*)(B + (size_t)brow0 * N + n0 + bnq);
    rb1 = *(const float4*)(B + (size_t)brow1 * N + n0 + bnq);
    {
        unsigned* d0 = &As[0][arow0][akq];
        d0[0]=f2tf(ra0.x); d0[1]=f2tf(ra0.y); d0[2]=f2tf(ra0.z); d0[3]=f2tf(ra0.w);
        unsigned* d1 = &As[0][arow1][akq];
        d1[0]=f2tf(ra1.x); d1[1]=f2tf(ra1.y); d1[2]=f2tf(ra1.z); d1[3]=f2tf(ra1.w);
        unsigned* e0 = &Bs[0][brow0][bnq];
        e0[0]=f2tf(rb0.x); e0[1]=f2tf(rb0.y); e0[2]=f2tf(rb0.z); e0[3]=f2tf(rb0.w);
        unsigned* e1 = &Bs[0][brow1][bnq];
        e1[0]=f2tf(rb1.x); e1[1]=f2tf(rb1.y); e1[2]=f2tf(rb1.z); e1[3]=f2tf(rb1.w);
    }
    __syncthreads();

    int cur = 0;
    for (int k0 = 0; k0 < K; k0 += BK) {
        const bool has_next = (k0 + BK) < K;
        if (has_next) {
            int kn = k0 + BK;
            ra0 = *(const float4*)(A + (size_t)(m0 + arow0) * K + kn + akq);
            ra1 = *(const float4*)(A + (size_t)(m0 + arow1) * K + kn + akq);
            rb0 = *(const float4*)(B + (size_t)(kn + brow0) * N + n0 + bnq);
            rb1 = *(const float4*)(B + (size_t)(kn + brow1) * N + n0 + bnq);
        }

        #pragma unroll
        for (int ks = 0; ks < 2; ++ks) {
            unsigned a[2][4], b[8][2];
            #pragma unroll
            for (int mt = 0; mt < 2; ++mt) {
                int r = wm + mt * 16;
                a[mt][0] = As[cur][r + g][ks * 8 + t];
                a[mt][1] = As[cur][r + g + 8][ks * 8 + t];
                a[mt][2] = As[cur][r + g][ks * 8 + t + 4];
                a[mt][3] = As[cur][r + g + 8][ks * 8 + t + 4];
            }
            #pragma unroll
            for (int nt = 0; nt < 8; ++nt) {
                b[nt][0] = Bs[cur][ks * 8 + t][wn + nt * 8 + g];
                b[nt][1] = Bs[cur][ks * 8 + t + 4][wn + nt * 8 + g];
            }
            #pragma unroll
            for (int mt = 0; mt < 2; ++mt)
                #pragma unroll
                for (int nt = 0; nt < 8; ++nt)
                    mma8(acc[mt][nt], a[mt], b[nt]);
        }

        if (has_next) {
            int nb = cur ^ 1;
            unsigned* d0 = &As[nb][arow0][akq];
            d0[0]=f2tf(ra0.x); d0[1]=f2tf(ra0.y); d0[2]=f2tf(ra0.z); d0[3]=f2tf(ra0.w);
            unsigned* d1 = &As[nb][arow1][akq];
            d1[0]=f2tf(ra1.x); d1[1]=f2tf(ra1.y); d1[2]=f2tf(ra1.z); d1[3]=f2tf(ra1.w);
            unsigned* e0 = &Bs[nb][brow0][bnq];
            e0[0]=f2tf(rb0.x); e0[1]=f2tf(rb0.y); e0[2]=f2tf(rb0.z); e0[3]=f2tf(rb0.w);
            unsigned* e1 = &Bs[nb][brow1][bnq];
            e1[0]=f2tf(rb1.x); e1[1]=f2tf(rb1.y); e1[2]=f2tf(rb1.z); e1[3]=f2tf(rb1.w);
            __syncthreads();
            cur = nb;
        }
    }

    #pragma unroll
    for (int mt = 0; mt < 2; ++mt) {
        int row = m0 + wm + mt * 16 + g;
        #pragma unroll
        for (int nt = 0; nt < 8; ++nt) {
            int col = n0 + wn + nt * 8 + 2 * t;
            float b0 = bias[col], b1 = bias[col + 1];
            *(float2*)(C + (size_t)row * N + col) =
                make_float2(acc[mt][nt][0] + b0, acc[mt][nt][1] + b1);
            *(float2*)(C + (size_t)(row + 8) * N + col) =
                make_float2(acc[mt][nt][2] + b0, acc[mt][nt][3] + b1);
        }
    }
}

// ---------------------------------------------------------------------------
// Flash attention, tf32 mma, double-buffered K/V tiles.
// Block = (head, 128-query tile); 8 warps x 16 query rows.
// ---------------------------------------------------------------------------
#define BQ 128
#define BKV 64
#define QSTR 68   // 68%32=4: banks 4g+t conflict-free
#define KSTR 68
#define VSTR 72   // 72%32=8: banks 8t+g conflict-free
#define PSTR 68

__global__ __launch_bounds__(256) void attn_tf32_kernel(
    const float* __restrict__ qkv, float* __restrict__ ctx)
{
    extern __shared__ unsigned smem[];
    unsigned* Qs = smem;                        // [128][QSTR]
    unsigned* Ks = Qs + BQ * QSTR;              // [2][64][KSTR]
    unsigned* Vs = Ks + 2 * BKV * KSTR;         // [2][64][VSTR]
    unsigned* Ps = Vs + 2 * BKV * VSTR;         // [8][16][PSTR]

    const int h  = blockIdx.y;
    const int qt = (int)gridDim.x - 1 - (int)blockIdx.x;   // heavy tiles first
    const int q0 = qt * BQ;
    const int tid = threadIdx.x;
    const int warp = tid >> 5, lane = tid & 31;
    const int g = lane >> 2, t = lane & 3;
    const int wm = warp * 16;
    unsigned* Pw = Ps + warp * 16 * PSTR;

    const float* kb = qkv + D_MODEL + h * HD;
    const float* vb = qkv + 2 * D_MODEL + h * HD;

    // Load Q tile (pre-scaled by 1/sqrt(HD) = 0.125), tf32
    const float* qb = qkv + (size_t)q0 * (3 * D_MODEL) + h * HD;
    for (int idx = tid; idx < BQ * 16; idx += 256) {
        int row = idx >> 4, dq = (idx & 15) << 2;
        float4 v = *(const float4*)(qb + (size_t)row * (3 * D_MODEL) + dq);
        unsigned* d = &Qs[row * QSTR + dq];
        d[0] = f2tf(v.x * 0.125f); d[1] = f2tf(v.y * 0.125f);
        d[2] = f2tf(v.z * 0.125f); d[3] = f2tf(v.w * 0.125f);
    }

    float m_[2] = {-1e30f, -1e30f};
    float l_[2] = {0.f, 0.f};
    float o[8][4];
    #pragma unroll
    for (int nt = 0; nt < 8; ++nt)
        #pragma unroll
        for (int i = 0; i < 4; ++i) o[nt][i] = 0.f;

    const int nkt = 2 * qt + 2;
    float4 pk[4], pv[4];

    // prologue: K/V tile 0 -> buf 0
    #pragma unroll
    for (int i = 0; i < 4; ++i) {
        int idx = tid + i * 256;
        int row = idx >> 4, dq = (idx & 15) << 2;
        size_t go = (size_t)row * (3 * D_MODEL) + dq;
        pk[i] = *(const float4*)(kb + go);
        pv[i] = *(const float4*)(vb + go);
    }
    #pragma unroll
    for (int i = 0; i < 4; ++i) {
        int idx = tid + i * 256;
        int row = idx >> 4, dq = (idx & 15) << 2;
        unsigned* kd = &Ks[row * KSTR + dq];
        kd[0]=f2tf(pk[i].x); kd[1]=f2tf(pk[i].y); kd[2]=f2tf(pk[i].z); kd[3]=f2tf(pk[i].w);
        unsigned* vd = &Vs[row * VSTR + dq];
        vd[0]=f2tf(pv[i].x); vd[1]=f2tf(pv[i].y); vd[2]=f2tf(pv[i].z); vd[3]=f2tf(pv[i].w);
    }
    __syncthreads();

    int cur = 0;
    for (int kt = 0; kt < nkt; ++kt) {
        const bool has_next = (kt + 1) < nkt;
        if (has_next) {
            #pragma unroll
            for (int i = 0; i < 4; ++i) {
                int idx = tid + i * 256;
                int row = idx >> 4, dq = (idx & 15) << 2;
                size_t go = (size_t)((kt + 1) * BKV + row) * (3 * D_MODEL) + dq;
                pk[i] = *(const float4*)(kb + go);
                pv[i] = *(const float4*)(vb + go);
            }
        }

        // Compute on buffer `cur` (skip if this warp's rows fully masked)
        if (kt * BKV <= q0 + wm + 15) {
            const unsigned* Kc = Ks + cur * BKV * KSTR;
            const unsigned* Vc = Vs + cur * BKV * VSTR;

            float s[8][4];
            #pragma unroll
            for (int nt = 0; nt < 8; ++nt)
                #pragma unroll
                for (int i = 0; i < 4; ++i) s[nt][i] = 0.f;

            #pragma unroll
            for (int ks = 0; ks < 8; ++ks) {
                unsigned a[4];
                a[0] = Qs[(wm + g) * QSTR + ks * 8 + t];
                a[1] = Qs[(wm + g + 8) * QSTR + ks * 8 + t];
                a[2] = Qs[(wm + g) * QSTR + ks * 8 + t + 4];
                a[3] = Qs[(wm + g + 8) * QSTR + ks * 8 + t + 4];
                #pragma unroll
                for (int nt = 0; nt < 8; ++nt) {
                    unsigned b[2];
                    b[0] = Kc[(nt * 8 + g) * KSTR + ks * 8 + t];
                    b[1] = Kc[(nt * 8 + g) * KSTR + ks * 8 + t + 4];
                    mma8(s[nt], a, b);
                }
            }

            // Causal mask (only the two diagonal k-tiles mask anything)
            if (kt >= 2 * qt) {
                int r0 = q0 + wm + g;
                #pragma unroll
                for (int nt = 0; nt < 8; ++nt) {
                    int col = kt * BKV + nt * 8 + 2 * t;
                    if (col     > r0)     s[nt][0] = -1e30f;
                    if (col + 1 > r0)     s[nt][1] = -1e30f;
                    if (col     > r0 + 8) s[nt][2] = -1e30f;
                    if (col + 1 > r0 + 8) s[nt][3] = -1e30f;
                }
            }

            // Online softmax (rows g, g+8; quad reduction over 4 lanes)
            #pragma unroll
            for (int r = 0; r < 2; ++r) {
                float tm = -1e30f;
                #pragma unroll
                for (int nt = 0; nt < 8; ++nt)
                    tm = fmaxf(tm, fmaxf(s[nt][2 * r], s[nt][2 * r + 1]));
                tm = fmaxf(tm, __shfl_xor_sync(0xffffffffu, tm, 1));
                tm = fmaxf(tm, __shfl_xor_sync(0xffffffffu, tm, 2));
                float mn = fmaxf(m_[r], tm);
                float rs = 0.f;
                #pragma unroll
                for (int nt = 0; nt < 8; ++nt) {
                    float p0 = __expf(s[nt][2 * r] - mn);
                    float p1 = __expf(s[nt][2 * r + 1] - mn);
                    s[nt][2 * r] = p0; s[nt][2 * r + 1] = p1;
                    rs += p0 + p1;
                }
                rs += __shfl_xor_sync(0xffffffffu, rs, 1);
                rs += __shfl_xor_sync(0xffffffffu, rs, 2);
                float alpha = __expf(m_[r] - mn);
                l_[r] = l_[r] * alpha + rs;
                #pragma unroll
                for (int nt = 0; nt < 8; ++nt) {
                    o[nt][2 * r] *= alpha; o[nt][2 * r + 1] *= alpha;
                }
                m_[r] = mn;
            }

            // P -> warp-private smem (tf32), then O += P V
            __syncwarp();
            #pragma unroll
            for (int nt = 0; nt < 8; ++nt) {
                unsigned* p0 = &Pw[g * PSTR + nt * 8 + 2 * t];
                p0[0] = f2tf(s[nt][0]); p0[1] = f2tf(s[nt][1]);
                unsigned* p1 = &Pw[(g + 8) * PSTR + nt * 8 + 2 * t];
                p1[0] = f2tf(s[nt][2]); p1[1] = f2tf(s[nt][3]);
            }
            __syncwarp();

            #pragma unroll
            for (int ks = 0; ks < 8; ++ks) {
                unsigned a[4];
                a[0] = Pw[g * PSTR + ks * 8 + t];
                a[1] = Pw[(g + 8) * PSTR + ks * 8 + t];
                a[2] = Pw[g * PSTR + ks * 8 + t + 4];
                a[3] = Pw[(g + 8) * PSTR + ks * 8 + t + 4];
                #pragma unroll
                for (int nt = 0; nt < 8; ++nt) {
                    unsigned b[2];
                    b[0] = Vc[(ks * 8 + t) * VSTR + nt * 8 + g];
                    b[1] = Vc[(ks * 8 + t + 4) * VSTR + nt * 8 + g];
                    mma8(o[nt], a, b);
                }
            }
        }

        if (has_next) {
            int nb = cur ^ 1;
            unsigned* Kn = Ks + nb * BKV * KSTR;
            unsigned* Vn = Vs + nb * BKV * VSTR;
            #pragma unroll
            for (int i = 0; i < 4; ++i) {
                int idx = tid + i * 256;
                int row = idx >> 4, dq = (idx & 15) << 2;
                unsigned* kd = &Kn[row * KSTR + dq];
                kd[0]=f2tf(pk[i].x); kd[1]=f2tf(pk[i].y); kd[2]=f2tf(pk[i].z); kd[3]=f2tf(pk[i].w);
                unsigned* vd = &Vn[row * VSTR + dq];
                vd[0]=f2tf(pv[i].x); vd[1]=f2tf(pv[i].y); vd[2]=f2tf(pv[i].z); vd[3]=f2tf(pv[i].w);
            }
            __syncthreads();
            cur = nb;
        }
    }

    // Epilogue: normalize and write ctx[q, h*64+d]
    float inv0 = 1.f / l_[0], inv1 = 1.f / l_[1];
    float* ob = ctx + (size_t)(q0 + wm) * D_MODEL + h * HD;
    #pragma unroll
    for (int nt = 0; nt < 8; ++nt) {
        int col = nt * 8 + 2 * t;
        *(float2*)(ob + (size_t)g * D_MODEL + col) =
            make_float2(o[nt][0] * inv0, o[nt][1] * inv0);
        *(float2*)(ob + (size_t)(g + 8) * D_MODEL + col) =
            make_float2(o[nt][2] * inv1, o[nt][3] * inv1);
    }
}

// ---------------------------------------------------------------------------
// Launch
// ---------------------------------------------------------------------------
extern "C" void kernel_launch(void* const* d_in, const int* in_sizes, int n_in,
                              void* d_out, int out_size)
{
    const float* x      = (const float*)d_in[0];
    const float* w_qkv  = (const float*)d_in[1];
    const float* b_qkv  = (const float*)d_in[2];
    const float* w_proj = (const float*)d_in[3];
    const float* b_proj = (const float*)d_in[4];
    float* out = (float*)d_out;

    float *qkv_ptr, *ctx_ptr;
    cudaGetSymbolAddress((void**)&qkv_ptr, g_qkv);
    cudaGetSymbolAddress((void**)&ctx_ptr, g_ctx);

    const int attn_smem =
        (BQ * QSTR + 2 * BKV * KSTR + 2 * BKV * VSTR + 8 * 16 * PSTR) * (int)sizeof(unsigned);
    cudaFuncSetAttribute(attn_tf32_kernel,
                         cudaFuncAttributeMaxDynamicSharedMemorySize, attn_smem);

    // 1) qkv = x @ w_qkv + b_qkv            [4096, 3072]
    gemm_tf32_kernel<<<dim3(3 * D_MODEL / BN, S_LEN / BM), 256>>>(
        x, w_qkv, b_qkv, qkv_ptr, S_LEN, 3 * D_MODEL, D_MODEL);

    // 2) causal flash attention -> ctx      [4096, 1024]
    attn_tf32_kernel<<<dim3(S_LEN / BQ, NH), 256, attn_smem>>>(qkv_ptr, ctx_ptr);

    // 3) out = ctx @ w_proj + b_proj        [4096, 1024]
    gemm_tf32_kernel<<<dim3(D_MODEL / BN, S_LEN / BM), 256>>>(
        ctx_ptr, w_proj, b_proj, out, S_LEN, D_MODEL, D_MODEL);
}

// round 8
// speedup vs baseline: 3.1836x; 1.1123x over previous
#include <cuda_runtime.h>
#include <math.h>

#define S_LEN 4096
#define D_MODEL 1024
#define NH 16
#define HD 64

// Scratch (allocation-free requirement -> __device__ globals)
__device__ float g_qkv[(size_t)S_LEN * 3 * D_MODEL];  // [S, 3D]
__device__ float g_ctx[(size_t)S_LEN * D_MODEL];      // [S, D]

// ---------------------------------------------------------------------------
// tf32 helpers
// ---------------------------------------------------------------------------
__device__ __forceinline__ unsigned f2tf(float f) {
    unsigned u;
    asm("cvt.rna.tf32.f32 %0, %1;" : "=r"(u) : "f"(f));
    return u;
}

__device__ __forceinline__ void mma8(float* d, const unsigned* a, const unsigned* b) {
    asm volatile("mma.sync.aligned.m16n8k8.row.col.f32.tf32.tf32.f32 "
        "{%0,%1,%2,%3}, {%4,%5,%6,%7}, {%8,%9}, {%0,%1,%2,%3};"
        : "+f"(d[0]), "+f"(d[1]), "+f"(d[2]), "+f"(d[3])
        : "r"(a[0]), "r"(a[1]), "r"(a[2]), "r"(a[3]), "r"(b[0]), "r"(b[1]));
}

// ---------------------------------------------------------------------------
// GEMM: C[M,N] = A[M,K] @ B[K,N] + bias  (fp32 in/out, tf32 mma)
// 128x128 block, BK=32, 256 threads (8 warps, 4x2), warp tile 32x64.
// Double-buffered smem, staged A-then-B register prefetch, 1 barrier/iter.
// ---------------------------------------------------------------------------
#define BM 128
#define BN 128
#define BK 32
#define ASTR 36    // 36%32=4: frag banks 4g+t distinct over warp
#define BSTR 136   // 136%32=8: frag banks 8t+g distinct over warp
#define A_TILE (BM * ASTR)   // 4608
#define B_TILE (BK * BSTR)   // 4352

__global__ __launch_bounds__(256, 2) void gemm_tf32_kernel(
    const float* __restrict__ A, const float* __restrict__ B,
    const float* __restrict__ bias, float* __restrict__ C,
    int M, int N, int K)
{
    extern __shared__ unsigned gsm[];
    unsigned* As = gsm;                 // [2][BM][ASTR]
    unsigned* Bs = gsm + 2 * A_TILE;    // [2][BK][BSTR]

    const int tid  = threadIdx.x;
    const int warp = tid >> 5, lane = tid & 31;
    const int g = lane >> 2, t = lane & 3;
    const int wm = (warp & 3) * 32;
    const int wn = (warp >> 2) * 64;
    const int m0 = blockIdx.y * BM, n0 = blockIdx.x * BN;

    // Loader slots: A: row = (tid>>3)+32p, cols aq..aq+3 ; B: row = warp+8p, cols bcg..+3
    const int arow = tid >> 3, aq = (tid & 7) << 2;
    const int brow = tid >> 5, bcg = (tid & 31) << 2;

    float acc[2][8][4];
    #pragma unroll
    for (int mt = 0; mt < 2; ++mt)
        #pragma unroll
        for (int nt = 0; nt < 8; ++nt)
            #pragma unroll
            for (int i = 0; i < 4; ++i) acc[mt][nt][i] = 0.f;

    float4 ra[4], rb[4];

    // prologue: tile 0 -> buf 0
    #pragma unroll
    for (int p = 0; p < 4; ++p) {
        ra[p] = *(const float4*)(A + (size_t)(m0 + arow + 32 * p) * K + aq);
        rb[p] = *(const float4*)(B + (size_t)(brow + 8 * p) * N + n0 + bcg);
    }
    #pragma unroll
    for (int p = 0; p < 4; ++p) {
        uint4 wa = make_uint4(f2tf(ra[p].x), f2tf(ra[p].y), f2tf(ra[p].z), f2tf(ra[p].w));
        *(uint4*)&As[(arow + 32 * p) * ASTR + aq] = wa;
        uint4 wb = make_uint4(f2tf(rb[p].x), f2tf(rb[p].y), f2tf(rb[p].z), f2tf(rb[p].w));
        *(uint4*)&Bs[(brow + 8 * p) * BSTR + bcg] = wb;
    }
    __syncthreads();

    int cur = 0;
    for (int k0 = 0; k0 < K; k0 += BK) {
        const bool hn = (k0 + BK) < K;
        const int kk = k0 + BK;

        if (hn) {
            #pragma unroll
            for (int p = 0; p < 4; ++p)
                ra[p] = *(const float4*)(A + (size_t)(m0 + arow + 32 * p) * K + kk + aq);
        }

        const unsigned* Ac = As + cur * A_TILE;
        const unsigned* Bc = Bs + cur * B_TILE;

        #pragma unroll
        for (int c = 0; c < 2; ++c) {
            unsigned a[2][4], b[8][2];
            #pragma unroll
            for (int mt = 0; mt < 2; ++mt) {
                int r = wm + mt * 16;
                a[mt][0] = Ac[(r + g) * ASTR + c * 8 + t];
                a[mt][1] = Ac[(r + g + 8) * ASTR + c * 8 + t];
                a[mt][2] = Ac[(r + g) * ASTR + c * 8 + t + 4];
                a[mt][3] = Ac[(r + g + 8) * ASTR + c * 8 + t + 4];
            }
            #pragma unroll
            for (int nt = 0; nt < 8; ++nt) {
                b[nt][0] = Bc[(c * 8 + t) * BSTR + wn + nt * 8 + g];
                b[nt][1] = Bc[(c * 8 + t + 4) * BSTR + wn + nt * 8 + g];
            }
            #pragma unroll
            for (int mt = 0; mt < 2; ++mt)
                #pragma unroll
                for (int nt = 0; nt < 8; ++nt)
                    mma8(acc[mt][nt], a[mt], b[nt]);
        }

        if (hn) {
            int nb = cur ^ 1;
            #pragma unroll
            for (int p = 0; p < 4; ++p) {
                uint4 wa = make_uint4(f2tf(ra[p].x), f2tf(ra[p].y), f2tf(ra[p].z), f2tf(ra[p].w));
                *(uint4*)&As[nb * A_TILE + (arow + 32 * p) * ASTR + aq] = wa;
                rb[p] = *(const float4*)(B + (size_t)(kk + brow + 8 * p) * N + n0 + bcg);
            }
        }

        #pragma unroll
        for (int c = 2; c < 4; ++c) {
            unsigned a[2][4], b[8][2];
            #pragma unroll
            for (int mt = 0; mt < 2; ++mt) {
                int r = wm + mt * 16;
                a[mt][0] = Ac[(r + g) * ASTR + c * 8 + t];
                a[mt][1] = Ac[(r + g + 8) * ASTR + c * 8 + t];
                a[mt][2] = Ac[(r + g) * ASTR + c * 8 + t + 4];
                a[mt][3] = Ac[(r + g + 8) * ASTR + c * 8 + t + 4];
            }
            #pragma unroll
            for (int nt = 0; nt < 8; ++nt) {
                b[nt][0] = Bc[(c * 8 + t) * BSTR + wn + nt * 8 + g];
                b[nt][1] = Bc[(c * 8 + t + 4) * BSTR + wn + nt * 8 + g];
            }
            #pragma unroll
            for (int mt = 0; mt < 2; ++mt)
                #pragma unroll
                for (int nt = 0; nt < 8; ++nt)
                    mma8(acc[mt][nt], a[mt], b[nt]);
        }

        if (hn) {
            int nb = cur ^ 1;
            #pragma unroll
            for (int p = 0; p < 4; ++p) {
                uint4 wb = make_uint4(f2tf(rb[p].x), f2tf(rb[p].y), f2tf(rb[p].z), f2tf(rb[p].w));
                *(uint4*)&Bs[nb * B_TILE + (brow + 8 * p) * BSTR + bcg] = wb;
            }
            __syncthreads();
            cur = nb;
        }
    }

    #pragma unroll
    for (int mt = 0; mt < 2; ++mt) {
        int row = m0 + wm + mt * 16 + g;
        #pragma unroll
        for (int nt = 0; nt < 8; ++nt) {
            int col = n0 + wn + nt * 8 + 2 * t;
            float b0 = bias[col], b1 = bias[col + 1];
            *(float2*)(C + (size_t)row * N + col) =
                make_float2(acc[mt][nt][0] + b0, acc[mt][nt][1] + b1);
            *(float2*)(C + (size_t)(row + 8) * N + col) =
                make_float2(acc[mt][nt][2] + b0, acc[mt][nt][3] + b1);
        }
    }
}

// ---------------------------------------------------------------------------
// Flash attention, tf32 mma. Block = (head, 128-query tile), 8 warps.
// Double-buffered K/V; P fragments via quad shuffles (no P smem) -> 2 CTAs/SM.
// ---------------------------------------------------------------------------
#define BQ 128
#define BKV 64
#define QSTR 68   // 68%32=4: banks 4g+t conflict-free
#define KSTR 68
#define VSTR 72   // 72%32=8: banks 8t+g conflict-free
#define Q_TILE (BQ * QSTR)    // 8704
#define K_TILE (BKV * KSTR)   // 4352
#define V_TILE (BKV * VSTR)   // 4608

__global__ __launch_bounds__(256, 2) void attn_tf32_kernel(
    const float* __restrict__ qkv, float* __restrict__ ctx)
{
    extern __shared__ unsigned smem[];
    unsigned* Qs = smem;                 // [128][QSTR]
    unsigned* Ks = smem + Q_TILE;        // [2][64][KSTR]
    unsigned* Vs = Ks + 2 * K_TILE;      // [2][64][VSTR]

    const int h  = blockIdx.y;
    const int qt = (int)gridDim.x - 1 - (int)blockIdx.x;   // heavy tiles first
    const int q0 = qt * BQ;
    const int tid = threadIdx.x;
    const int warp = tid >> 5, lane = tid & 31;
    const int g = lane >> 2, t = lane & 3;
    const int wm = warp * 16;

    const float* kb = qkv + D_MODEL + h * HD;
    const float* vb = qkv + 2 * D_MODEL + h * HD;

    // Load Q tile (pre-scaled by 1/sqrt(HD) = 0.125), tf32
    const float* qb = qkv + (size_t)q0 * (3 * D_MODEL) + h * HD;
    for (int idx = tid; idx < BQ * 16; idx += 256) {
        int row = idx >> 4, dq = (idx & 15) << 2;
        float4 v = *(const float4*)(qb + (size_t)row * (3 * D_MODEL) + dq);
        uint4 w = make_uint4(f2tf(v.x * 0.125f), f2tf(v.y * 0.125f),
                             f2tf(v.z * 0.125f), f2tf(v.w * 0.125f));
        *(uint4*)&Qs[row * QSTR + dq] = w;
    }

    float m_[2] = {-1e30f, -1e30f};
    float l_[2] = {0.f, 0.f};
    float o[8][4];
    #pragma unroll
    for (int nt = 0; nt < 8; ++nt)
        #pragma unroll
        for (int i = 0; i < 4; ++i) o[nt][i] = 0.f;

    const int nkt = 2 * qt + 2;
    float4 r4[4];

    // prologue: K/V tile 0 -> buf 0
    #pragma unroll
    for (int i = 0; i < 4; ++i) {
        int idx = tid + i * 256;
        int row = idx >> 4, dq = (idx & 15) << 2;
        r4[i] = *(const float4*)(kb + (size_t)row * (3 * D_MODEL) + dq);
    }
    #pragma unroll
    for (int i = 0; i < 4; ++i) {
        int idx = tid + i * 256;
        int row = idx >> 4, dq = (idx & 15) << 2;
        uint4 w = make_uint4(f2tf(r4[i].x), f2tf(r4[i].y), f2tf(r4[i].z), f2tf(r4[i].w));
        *(uint4*)&Ks[row * KSTR + dq] = w;
        r4[i] = *(const float4*)(vb + (size_t)row * (3 * D_MODEL) + dq);
    }
    #pragma unroll
    for (int i = 0; i < 4; ++i) {
        int idx = tid + i * 256;
        int row = idx >> 4, dq = (idx & 15) << 2;
        uint4 w = make_uint4(f2tf(r4[i].x), f2tf(r4[i].y), f2tf(r4[i].z), f2tf(r4[i].w));
        *(uint4*)&Vs[row * VSTR + dq] = w;
    }
    __syncthreads();

    int cur = 0;
    const int src0 = (lane & ~3) | (t >> 1);   // owner quad-lane of P col (k%8)=t
    const bool odd = (t & 1);

    for (int kt = 0; kt < nkt; ++kt) {
        const bool hn = (kt + 1) < nkt;
        const bool active = (kt * BKV <= q0 + wm + 15);
        float s[8][4];

        if (hn) {
            #pragma unroll
            for (int i = 0; i < 4; ++i) {
                int idx = tid + i * 256;
                int row = idx >> 4, dq = (idx & 15) << 2;
                r4[i] = *(const float4*)(kb + (size_t)((kt + 1) * BKV + row) * (3 * D_MODEL) + dq);
            }
        }

        const unsigned* Kc = Ks + cur * K_TILE;
        const unsigned* Vc = Vs + cur * V_TILE;

        if (active) {
            // S = Q K^T   (16 x 64 per warp)
            #pragma unroll
            for (int nt = 0; nt < 8; ++nt)
                #pragma unroll
                for (int i = 0; i < 4; ++i) s[nt][i] = 0.f;

            #pragma unroll
            for (int ks = 0; ks < 8; ++ks) {
                unsigned a[4];
                a[0] = Qs[(wm + g) * QSTR + ks * 8 + t];
                a[1] = Qs[(wm + g + 8) * QSTR + ks * 8 + t];
                a[2] = Qs[(wm + g) * QSTR + ks * 8 + t + 4];
                a[3] = Qs[(wm + g + 8) * QSTR + ks * 8 + t + 4];
                #pragma unroll
                for (int nt = 0; nt < 8; ++nt) {
                    unsigned b[2];
                    b[0] = Kc[(nt * 8 + g) * KSTR + ks * 8 + t];
                    b[1] = Kc[(nt * 8 + g) * KSTR + ks * 8 + t + 4];
                    mma8(s[nt], a, b);
                }
            }

            // Causal mask (only diagonal k-tiles mask anything)
            if (kt >= 2 * qt) {
                int r0 = q0 + wm + g;
                #pragma unroll
                for (int nt = 0; nt < 8; ++nt) {
                    int col = kt * BKV + nt * 8 + 2 * t;
                    if (col     > r0)     s[nt][0] = -1e30f;
                    if (col + 1 > r0)     s[nt][1] = -1e30f;
                    if (col     > r0 + 8) s[nt][2] = -1e30f;
                    if (col + 1 > r0 + 8) s[nt][3] = -1e30f;
                }
            }

            // Online softmax (rows g, g+8; quad reduction over 4 lanes)
            #pragma unroll
            for (int r = 0; r < 2; ++r) {
                float tm = -1e30f;
                #pragma unroll
                for (int nt = 0; nt < 8; ++nt)
                    tm = fmaxf(tm, fmaxf(s[nt][2 * r], s[nt][2 * r + 1]));
                tm = fmaxf(tm, __shfl_xor_sync(0xffffffffu, tm, 1));
                tm = fmaxf(tm, __shfl_xor_sync(0xffffffffu, tm, 2));
                float mn = fmaxf(m_[r], tm);
                float rs = 0.f;
                #pragma unroll
                for (int nt = 0; nt < 8; ++nt) {
                    float p0 = __expf(s[nt][2 * r] - mn);
                    float p1 = __expf(s[nt][2 * r + 1] - mn);
                    s[nt][2 * r] = p0; s[nt][2 * r + 1] = p1;
                    rs += p0 + p1;
                }
                rs += __shfl_xor_sync(0xffffffffu, rs, 1);
                rs += __shfl_xor_sync(0xffffffffu, rs, 2);
                float alpha = __expf(m_[r] - mn);
                l_[r] = l_[r] * alpha + rs;
                #pragma unroll
                for (int nt = 0; nt < 8; ++nt) {
                    o[nt][2 * r] *= alpha; o[nt][2 * r + 1] *= alpha;
                }
                m_[r] = mn;
            }
        }

        if (hn) {
            int nb = cur ^ 1;
            #pragma unroll
            for (int i = 0; i < 4; ++i) {
                int idx = tid + i * 256;
                int row = idx >> 4, dq = (idx & 15) << 2;
                uint4 w = make_uint4(f2tf(r4[i].x), f2tf(r4[i].y), f2tf(r4[i].z), f2tf(r4[i].w));
                *(uint4*)&Ks[nb * K_TILE + row * KSTR + dq] = w;
                r4[i] = *(const float4*)(vb + (size_t)((kt + 1) * BKV + row) * (3 * D_MODEL) + dq);
            }
        }

        if (active) {
            // O += P V : P fragment gathered from s regs via quad shuffles.
            // P[row][k] owner lane = (g*4) + (k%8)/2, component (k&1) within s[k/8].
            #pragma unroll
            for (int ks = 0; ks < 8; ++ks) {
                float x0 = __shfl_sync(0xffffffffu, s[ks][0], src0);
                float x1 = __shfl_sync(0xffffffffu, s[ks][1], src0);
                float y0 = __shfl_sync(0xffffffffu, s[ks][2], src0);
                float y1 = __shfl_sync(0xffffffffu, s[ks][3], src0);
                float x2 = __shfl_sync(0xffffffffu, s[ks][0], src0 + 2);
                float x3 = __shfl_sync(0xffffffffu, s[ks][1], src0 + 2);
                float y2 = __shfl_sync(0xffffffffu, s[ks][2], src0 + 2);
                float y3 = __shfl_sync(0xffffffffu, s[ks][3], src0 + 2);
                unsigned a[4];
                a[0] = f2tf(odd ? x1 : x0);
                a[1] = f2tf(odd ? y1 : y0);
                a[2] = f2tf(odd ? x3 : x2);
                a[3] = f2tf(odd ? y3 : y2);
                #pragma unroll
                for (int nt = 0; nt < 8; ++nt) {
                    unsigned b[2];
                    b[0] = Vc[(ks * 8 + t) * VSTR + nt * 8 + g];
                    b[1] = Vc[(ks * 8 + t + 4) * VSTR + nt * 8 + g];
                    mma8(o[nt], a, b);
                }
            }
        }

        if (hn) {
            int nb = cur ^ 1;
            #pragma unroll
            for (int i = 0; i < 4; ++i) {
                int idx = tid + i * 256;
                int row = idx >> 4, dq = (idx & 15) << 2;
                uint4 w = make_uint4(f2tf(r4[i].x), f2tf(r4[i].y), f2tf(r4[i].z), f2tf(r4[i].w));
                *(uint4*)&Vs[nb * V_TILE + row * VSTR + dq] = w;
            }
            __syncthreads();
            cur = nb;
        }
    }

    // Epilogue: normalize and write ctx[q, h*64+d]
    float inv0 = 1.f / l_[0], inv1 = 1.f / l_[1];
    float* ob = ctx + (size_t)(q0 + wm) * D_MODEL + h * HD;
    #pragma unroll
    for (int nt = 0; nt < 8; ++nt) {
        int col = nt * 8 + 2 * t;
        *(float2*)(ob + (size_t)g * D_MODEL + col) =
            make_float2(o[nt][0] * inv0, o[nt][1] * inv0);
        *(float2*)(ob + (size_t)(g + 8) * D_MODEL + col) =
            make_float2(o[nt][2] * inv1, o[nt][3] * inv1);
    }
}

// ---------------------------------------------------------------------------
// Launch
// ---------------------------------------------------------------------------
extern "C" void kernel_launch(void* const* d_in, const int* in_sizes, int n_in,
                              void* d_out, int out_size)
{
    const float* x      = (const float*)d_in[0];
    const float* w_qkv  = (const float*)d_in[1];
    const float* b_qkv  = (const float*)d_in[2];
    const float* w_proj = (const float*)d_in[3];
    const float* b_proj = (const float*)d_in[4];
    float* out = (float*)d_out;

    float *qkv_ptr, *ctx_ptr;
    cudaGetSymbolAddress((void**)&qkv_ptr, g_qkv);
    cudaGetSymbolAddress((void**)&ctx_ptr, g_ctx);

    const int gemm_smem = (2 * A_TILE + 2 * B_TILE) * (int)sizeof(unsigned);   // 71680
    const int attn_smem = (Q_TILE + 2 * K_TILE + 2 * V_TILE) * (int)sizeof(unsigned); // 106496
    cudaFuncSetAttribute(gemm_tf32_kernel,
                         cudaFuncAttributeMaxDynamicSharedMemorySize, gemm_smem);
    cudaFuncSetAttribute(attn_tf32_kernel,
                         cudaFuncAttributeMaxDynamicSharedMemorySize, attn_smem);

    // 1) qkv = x @ w_qkv + b_qkv            [4096, 3072]
    gemm_tf32_kernel<<<dim3(3 * D_MODEL / BN, S_LEN / BM), 256, gemm_smem>>>(
        x, w_qkv, b_qkv, qkv_ptr, S_LEN, 3 * D_MODEL, D_MODEL);

    // 2) causal flash attention -> ctx      [4096, 1024]
    attn_tf32_kernel<<<dim3(S_LEN / BQ, NH), 256, attn_smem>>>(qkv_ptr, ctx_ptr);

    // 3) out = ctx @ w_proj + b_proj        [4096, 1024]
    gemm_tf32_kernel<<<dim3(D_MODEL / BN, S_LEN / BM), 256, gemm_smem>>>(
        ctx_ptr, w_proj, b_proj, out, S_LEN, D_MODEL, D_MODEL);
}